// round 14
// baseline (speedup 1.0000x reference)
#include <cuda_runtime.h>
#include <cstdint>

// Attention_18021682774359: BiDAF-style context-query attention.
// B=64, CL=400, QL=50, H=1024. Output [B, CL, 4H] fp32.
//
// Round 14 (round 13 + dynamic smem fix): s2 never materialized. k_s2red
// computes per-(b,j) slab partials (masked online max/sum over G columns);
// K3 combines partials in its prologue and converts staged G tiles to
// softmax weights in shared memory. k_s2tc needs 50432 B shared -> dynamic
// smem + cudaFuncSetAttribute (host attribute call; graph-capture safe).

namespace {
constexpr int B_  = 64;
constexpr int CL_ = 400;
constexpr int QL_ = 50;
constexpr int H_  = 1024;
constexpr int QS_ = 64;   // padded QL
constexpr int SMEM_S2TC = 16384 + 32768 + 256 + 256 + 256 + 256 + 256; // 50432
}

// -------- scratch (device globals; allocation-free) --------
__device__ float g_G    [B_*CL_*QS_];
__device__ float g_s1   [B_*CL_*QS_];
__device__ float g_qpad [B_*QS_*H_];    // raw q, zero-padded rows
__device__ float g_qpadw[B_*QS_*H_];    // q * cqw, zero-padded rows
__device__ float g_t    [B_*QS_*H_];
__device__ float g_cdot [B_*CL_];
__device__ float g_qdot [B_*QS_];
__device__ float g_pM   [B_*8*QS_];     // soft2 slab partial max
__device__ float g_pS   [B_*8*QS_];     // soft2 slab partial sum

__device__ __forceinline__ unsigned smem_u32(const void* p) {
    return (unsigned)__cvta_generic_to_shared(p);
}
__device__ __forceinline__ void cp_async16(unsigned dst, const void* src, bool pred) {
    int sz = pred ? 16 : 0;
    asm volatile("cp.async.cg.shared.global [%0], [%1], 16, %2;"
                 :: "r"(dst), "l"(src), "r"(sz) : "memory");
}
__device__ __forceinline__ void cp_commit() {
    asm volatile("cp.async.commit_group;" ::: "memory");
}

// ============================================================
// K0: zero-padded q copies + fused qdot (block == one (b,j) row)
// ============================================================
__global__ __launch_bounds__(256) void k_qpad(
    const float* __restrict__ q, const float* __restrict__ cqw,
    const float* __restrict__ qw)
{
    __shared__ float red[8];
    int blk = blockIdx.x;            // b*64 + j
    int j = blk & 63, b = blk >> 6;
    int h4 = threadIdx.x;            // 0..255 float4 position
    float4 v = make_float4(0.f, 0.f, 0.f, 0.f);
    if (j < QL_) v = ((const float4*)q)[((b * QL_ + j) << 8) + h4];
    int idx = (blk << 8) + h4;
    ((float4*)g_qpad)[idx] = v;
    float4 w = ((const float4*)cqw)[h4];
    ((float4*)g_qpadw)[idx] = make_float4(v.x*w.x, v.y*w.y, v.z*w.z, v.w*w.w);

    float4 ww = ((const float4*)qw)[h4];
    float s = v.x*ww.x + v.y*ww.y + v.z*ww.z + v.w*ww.w;
#pragma unroll
    for (int o = 16; o; o >>= 1) s += __shfl_xor_sync(0xffffffffu, s, o);
    int lane = threadIdx.x & 31, wid = threadIdx.x >> 5;
    if (lane == 0) red[wid] = s;
    __syncthreads();
    if (threadIdx.x == 0) {
        float t = 0.f;
#pragma unroll
        for (int r = 0; r < 8; r++) t += red[r];
        g_qdot[blk] = t;
    }
}

// ============================================================
// K1: G[b, i-tile 64, j 64] = c @ qpadw^T, K=1024 (32 chunks of 32).
// 64 threads, micro 8x8, k-vectorized, crosswise swizzle, cp.async.
// Fused: tx==0 lanes accumulate cdot = c . cw from the resident A-tile.
// ============================================================
__global__ __launch_bounds__(64) void k_simgemm(
    const float* __restrict__ c, const float* __restrict__ cw)
{
    __shared__ float4 As4[2][512];   // 64 rows x 8 kgroups
    __shared__ float4 Bs4[2][512];
    __shared__ float4 CwS[2][8];
    int b  = blockIdx.y;
    int i0 = blockIdx.x * 64;
    int tid = threadIdx.x, tx = tid & 7, ty = tid >> 3;
    const float* cb = c        + (size_t)b * CL_ * H_;
    const float* qb = g_qpadw  + (size_t)b * QS_ * H_;

    float acc[8][8];
#pragma unroll
    for (int i = 0; i < 8; i++)
#pragma unroll
        for (int j = 0; j < 8; j++) acc[i][j] = 0.f;
    float cd[8];
#pragma unroll
    for (int i = 0; i < 8; i++) cd[i] = 0.f;

    auto stage = [&](int ch, int buf) {
        int kc = ch * 32;
#pragma unroll
        for (int u = 0; u < 8; u++) {
            int idx = tid + 64 * u;
            int m = idx >> 3, kg = idx & 7;
            bool p = (i0 + m) < CL_;
            const float* src = cb + (size_t)(p ? (i0 + m) : 0) * H_ + kc + kg * 4;
            cp_async16(smem_u32(&As4[buf][m * 8 + (kg ^ ((m >> 2) & 7))]), src, p);
        }
#pragma unroll
        for (int u = 0; u < 8; u++) {
            int idx = tid + 64 * u;
            int n = idx >> 3, kg = idx & 7;
            cp_async16(smem_u32(&Bs4[buf][n * 8 + (kg ^ ((n >> 2) & 7))]),
                       qb + (size_t)n * H_ + kc + kg * 4, true);
        }
        if (tid < 8) cp_async16(smem_u32(&CwS[buf][tid]), cw + kc + tid * 4, true);
        cp_commit();
    };

    stage(0, 0);
    for (int ch = 0; ch < 32; ch++) {
        int buf = ch & 1;
        if (ch < 31) {
            stage(ch + 1, buf ^ 1);
            asm volatile("cp.async.wait_group 1;" ::: "memory");
        } else {
            asm volatile("cp.async.wait_group 0;" ::: "memory");
        }
        __syncthreads();
#pragma unroll 1
        for (int kg = 0; kg < 8; kg++) {
            float4 a4[8], b4[8];
#pragma unroll
            for (int ii = 0; ii < 4; ii++) {
                a4[ii]     = As4[buf][(ty * 4 + ii)      * 8 + (kg ^ ty)];
                a4[ii + 4] = As4[buf][(ty * 4 + 32 + ii) * 8 + (kg ^ ty)];
                b4[ii]     = Bs4[buf][(tx * 4 + ii)      * 8 + (kg ^ tx)];
                b4[ii + 4] = Bs4[buf][(tx * 4 + 32 + ii) * 8 + (kg ^ tx)];
            }
            if (tx == 0) {
                float4 w4 = CwS[buf][kg];
#pragma unroll
                for (int ii = 0; ii < 8; ii++)
                    cd[ii] += a4[ii].x*w4.x + a4[ii].y*w4.y + a4[ii].z*w4.z + a4[ii].w*w4.w;
            }
#pragma unroll
            for (int ii = 0; ii < 8; ii++)
#pragma unroll
                for (int jj = 0; jj < 8; jj++) {
                    acc[ii][jj] += a4[ii].x * b4[jj].x + a4[ii].y * b4[jj].y
                                 + a4[ii].z * b4[jj].z + a4[ii].w * b4[jj].w;
                }
        }
        __syncthreads();
    }

#pragma unroll
    for (int ii = 0; ii < 8; ii++) {
        int gi = i0 + ty * 4 + (ii & 3) + ((ii >= 4) ? 32 : 0);
        if (gi < CL_) {
            float* g = g_G + ((size_t)(b * CL_ + gi) << 6);
            *(float4*)(g + tx * 4)      = make_float4(acc[ii][0], acc[ii][1], acc[ii][2], acc[ii][3]);
            *(float4*)(g + tx * 4 + 32) = make_float4(acc[ii][4], acc[ii][5], acc[ii][6], acc[ii][7]);
        }
    }
    if (tx == 0) {
#pragma unroll
        for (int ii = 0; ii < 8; ii++) {
            int gi = i0 + ty * 4 + (ii & 3) + ((ii >= 4) ? 32 : 0);
            if (gi < CL_) g_cdot[b * CL_ + gi] = cd[ii];
        }
    }
}

// ============================================================
// K2a: softmax over q dim (warp per (b,i) row).
// ============================================================
__global__ __launch_bounds__(256) void k_soft1(
    const int* __restrict__ qmask, const float* __restrict__ bias)
{
    int gw   = (blockIdx.x * 256 + threadIdx.x) >> 5;
    int lane = threadIdx.x & 31;
    if (gw >= B_ * CL_) return;
    int b = gw / CL_;
    float bi = bias[0];
    float cd = g_cdot[gw];
    const float* Grow = g_G + ((size_t)gw << 6);

    int j1 = lane, j2 = lane + 32;
    float v1 = qmask[b * QL_ + j1] ? (Grow[j1] + cd + g_qdot[b*QS_ + j1] + bi) : -1e30f;
    float v2 = -1e38f;
    if (j2 < QL_) v2 = qmask[b * QL_ + j2] ? (Grow[j2] + cd + g_qdot[b*QS_ + j2] + bi) : -1e30f;

    float mx = fmaxf(v1, v2);
#pragma unroll
    for (int o = 16; o; o >>= 1) mx = fmaxf(mx, __shfl_xor_sync(0xffffffffu, mx, o));
    float e1 = expf(v1 - mx);
    float e2 = (j2 < QL_) ? expf(v2 - mx) : 0.f;
    float s = e1 + e2;
#pragma unroll
    for (int o = 16; o; o >>= 1) s += __shfl_xor_sync(0xffffffffu, s, o);
    float inv = 1.f / s;

    float* s1row = g_s1 + ((size_t)gw << 6);
    s1row[j1] = e1 * inv;
    s1row[j2] = (j2 < QL_) ? e2 * inv : 0.f;
}

// ============================================================
// K2b: s2 column-softmax REDUCTION ONLY. Block (b, z): rows [z*50,(z+1)*50).
// 256 threads = 4 r x 64 j. Coalesced masked online max/sum -> g_pM/g_pS.
// ============================================================
__global__ __launch_bounds__(256) void k_s2red(
    const int* __restrict__ cmask, const float* __restrict__ bias)
{
    __shared__ float Ms[4][64], Ss[4][64];
    int blk = blockIdx.x;            // b*8 + z
    int z = blk & 7, b = blk >> 3;
    int j = threadIdx.x & 63;
    int r = threadIdx.x >> 6;        // 0..3
    float qd = g_qdot[b * QS_ + j] + bias[0];

    float m = -1e38f, s = 0.f;
    int i1 = (z + 1) * 50;
    for (int i = z * 50 + r; i < i1; i += 4) {
        float v = g_G[((size_t)(b * CL_ + i) << 6) + j] + g_cdot[b * CL_ + i] + qd;
        v = cmask[b * CL_ + i] ? v : -1e30f;
        if (v > m) { s = s * expf(m - v) + 1.f; m = v; }
        else       { s += expf(v - m); }
    }
    Ms[r][j] = m; Ss[r][j] = s;
    __syncthreads();
    if (r == 0) {
        float M = Ms[0][j], S = Ss[0][j];
#pragma unroll
        for (int u = 1; u < 4; u++) {
            float m2 = Ms[u][j], s2 = Ss[u][j];
            if (m2 > M) { S = S * expf(M - m2) + s2; M = m2; }
            else        { S += s2 * expf(m2 - M); }
        }
        g_pM[blk * QS_ + j] = M;
        g_pS[blk * QS_ + j] = S;
    }
}

// ============================================================
// K3: t[b, j 64, h-tile 128] = softmax_c(G)^T @ c. s2 computed INLINE:
// stage G tiles, transform in smem to exp(v-M)/S with masking/padding.
// 128 threads, micro 8x8, outer-product, cp.async. Dynamic smem (50432 B).
// ============================================================
__global__ __launch_bounds__(128) void k_s2tc(
    const float* __restrict__ c, const int* __restrict__ cmask,
    const float* __restrict__ bias)
{
    extern __shared__ __align__(16) char smem[];
    float4* As4   = (float4*)smem;                 // 2 x 512
    float4* Bs4   = As4 + 1024;                    // 2 x 1024
    float*  cdotS = (float*)(Bs4 + 2048);          // 2 x 32
    int*    cmS   = (int*)(cdotS + 64);            // 2 x 32
    float*  Mj    = (float*)(cmS + 64);            // 64
    float*  iSj   = Mj + 64;                       // 64
    float*  qdj   = iSj + 64;                      // 64

    int b  = blockIdx.y;
    int h0 = blockIdx.x * 128;
    int tid = threadIdx.x, tx = tid & 15, ty = tid >> 4;

    // prologue: combine the 8 slab partials -> M, 1/S per j; cache qdot+bias
    if (tid < 64) {
        float M = g_pM[(b * 8) * QS_ + tid];
        float S = g_pS[(b * 8) * QS_ + tid];
#pragma unroll
        for (int u = 1; u < 8; u++) {
            float m2 = g_pM[(b * 8 + u) * QS_ + tid];
            float s2 = g_pS[(b * 8 + u) * QS_ + tid];
            if (m2 > M) { S = S * expf(M - m2) + s2; M = m2; }
            else        { S += s2 * expf(m2 - M); }
        }
        Mj[tid] = M; iSj[tid] = 1.f / S;
        qdj[tid] = g_qdot[b * QS_ + tid] + bias[0];
    }

    float acc[8][8];
#pragma unroll
    for (int i = 0; i < 8; i++)
#pragma unroll
        for (int j = 0; j < 8; j++) acc[i][j] = 0.f;

    auto stage = [&](int ch, int buf) {
        int kc = ch * 32;
#pragma unroll
        for (int u = 0; u < 4; u++) {
            int idx = tid + 128 * u;
            int il = idx >> 4, jg = idx & 15;
            bool p = (kc + il) < CL_;
            const float* src = g_G + ((size_t)(b * CL_ + (p ? kc + il : 0)) << 6) + jg * 4;
            cp_async16(smem_u32(&As4[buf * 512 + il * 16 + (jg ^ ((il >> 2) & 7))]), src, p);
        }
#pragma unroll
        for (int u = 0; u < 8; u++) {
            int idx = tid + 128 * u;
            int il = idx >> 5, hg = idx & 31;
            bool p = (kc + il) < CL_;
            const float* src = c + (size_t)(b * CL_ + (p ? kc + il : 0)) * H_ + h0 + hg * 4;
            cp_async16(smem_u32(&Bs4[buf * 1024 + il * 32 + (hg ^ ((il >> 2) & 7))]), src, p);
        }
        if (tid < 32) {
            int gi = kc + tid;
            bool p = gi < CL_;
            cdotS[buf * 32 + tid] = p ? g_cdot[b * CL_ + gi] : 0.f;
            cmS[buf * 32 + tid]   = p ? cmask[b * CL_ + gi] : 0;
        }
        cp_commit();
    };

    stage(0, 0);
    for (int ch = 0; ch < 13; ch++) {
        int buf = ch & 1;
        if (ch < 12) {
            stage(ch + 1, buf ^ 1);
            asm volatile("cp.async.wait_group 1;" ::: "memory");
        } else {
            asm volatile("cp.async.wait_group 0;" ::: "memory");
        }
        __syncthreads();
        // ---- transform staged G tile -> s2 weights (in place) ----
        {
            int kc = ch * 32;
#pragma unroll
            for (int u = 0; u < 4; u++) {
                int idx = tid + 128 * u;
                int il = idx >> 4, jg = idx & 15;
                int pos = buf * 512 + il * 16 + (jg ^ ((il >> 2) & 7));
                float4 g4 = As4[pos];
                bool rowin = (kc + il) < CL_;
                bool rowok = rowin && cmS[buf * 32 + il];
                float cd = cdotS[buf * 32 + il];
                int j0 = jg * 4;
                float4 r4;
                float vv;
                vv  = rowok ? (g4.x + cd + qdj[j0+0]) : -1e30f;
                r4.x = (rowin && (j0+0) < QL_) ? expf(vv - Mj[j0+0]) * iSj[j0+0] : 0.f;
                vv  = rowok ? (g4.y + cd + qdj[j0+1]) : -1e30f;
                r4.y = (rowin && (j0+1) < QL_) ? expf(vv - Mj[j0+1]) * iSj[j0+1] : 0.f;
                vv  = rowok ? (g4.z + cd + qdj[j0+2]) : -1e30f;
                r4.z = (rowin && (j0+2) < QL_) ? expf(vv - Mj[j0+2]) * iSj[j0+2] : 0.f;
                vv  = rowok ? (g4.w + cd + qdj[j0+3]) : -1e30f;
                r4.w = (rowin && (j0+3) < QL_) ? expf(vv - Mj[j0+3]) * iSj[j0+3] : 0.f;
                As4[pos] = r4;
            }
        }
        __syncthreads();
#pragma unroll 4
        for (int kk = 0; kk < 32; kk++) {
            int s = (kk >> 2) & 7;
            float4 a0 = As4[buf * 512 + kk * 16 + (ty ^ s)];
            float4 a1 = As4[buf * 512 + kk * 16 + ((ty + 8) ^ s)];
            float4 b0 = Bs4[buf * 1024 + kk * 32 + (tx ^ s)];
            float4 b1 = Bs4[buf * 1024 + kk * 32 + ((tx + 16) ^ s)];
            float av[8] = {a0.x,a0.y,a0.z,a0.w, a1.x,a1.y,a1.z,a1.w};
            float bv[8] = {b0.x,b0.y,b0.z,b0.w, b1.x,b1.y,b1.z,b1.w};
#pragma unroll
            for (int ii = 0; ii < 8; ii++)
#pragma unroll
                for (int jj = 0; jj < 8; jj++) acc[ii][jj] += av[ii] * bv[jj];
        }
        __syncthreads();
    }

#pragma unroll
    for (int ii = 0; ii < 8; ii++) {
        int j = ty * 4 + (ii & 3) + ((ii >= 4) ? 32 : 0);
        float* gt = g_t + (size_t)(b * QS_ + j) * H_ + h0;
        *(float4*)(gt + tx * 4)      = make_float4(acc[ii][0], acc[ii][1], acc[ii][2], acc[ii][3]);
        *(float4*)(gt + tx * 4 + 64) = make_float4(acc[ii][4], acc[ii][5], acc[ii][6], acc[ii][7]);
    }
}

// ============================================================
// K4: a = s1 @ qpad, bb = s1 @ t (K=64 resident), fused epilogue
//     out = [c, a, c*a, c*bb]. 128 threads, dual micro 8x4.
// ============================================================
__global__ __launch_bounds__(128) void k_out(
    const float* __restrict__ c, float* __restrict__ out)
{
    __shared__ float  As[64][64];    // [j][i] swizzled (s1^T)
    __shared__ float4 BQ4[1024];     // [j][h-groups 16]
    __shared__ float4 BT4[1024];
    int b  = blockIdx.z;
    int h0 = blockIdx.y * 64;
    int i0 = blockIdx.x * 64;
    int tid = threadIdx.x, tx = tid & 15, ty = tid >> 4;
    const float* cb = c + (size_t)b * CL_ * H_;

#pragma unroll
    for (int u = 0; u < 8; u++) {
        int idx = tid + 128 * u;
        int il = idx >> 4, jg = idx & 15;
        int gi = i0 + il;
        float4 v = make_float4(0.f, 0.f, 0.f, 0.f);
        if (gi < CL_) v = *(const float4*)(g_s1 + ((size_t)(b * CL_ + gi) << 6) + jg * 4);
        int colb = (((il >> 2) ^ (jg & 7)) << 2) | (il & 3);
        As[jg*4+0][colb] = v.x; As[jg*4+1][colb] = v.y;
        As[jg*4+2][colb] = v.z; As[jg*4+3][colb] = v.w;
    }
#pragma unroll
    for (int u = 0; u < 8; u++) {
        int idx = tid + 128 * u;
        int jl = idx >> 4, hg = idx & 15;
        size_t src = (size_t)(b * QS_ + jl) * H_ + h0 + hg * 4;
        int d = jl * 16 + (hg ^ ((jl >> 2) & 7));
        BQ4[d] = *(const float4*)(g_qpad + src);
        BT4[d] = *(const float4*)(g_t + src);
    }
    __syncthreads();

    float accA[8][4], accB[8][4];
#pragma unroll
    for (int i = 0; i < 8; i++)
#pragma unroll
        for (int j = 0; j < 4; j++) { accA[i][j] = 0.f; accB[i][j] = 0.f; }

#pragma unroll 4
    for (int kk = 0; kk < 64; kk++) {
        int s = (kk >> 2) & 7;
        float4 a0 = *(const float4*)&As[kk][(ty ^ s) << 2];
        float4 a1 = *(const float4*)&As[kk][((ty + 8) ^ s) << 2];
        float4 q  = BQ4[kk * 16 + (tx ^ s)];
        float4 t  = BT4[kk * 16 + (tx ^ s)];
        float av[8] = {a0.x,a0.y,a0.z,a0.w, a1.x,a1.y,a1.z,a1.w};
        float qv[4] = {q.x, q.y, q.z, q.w};
        float tv[4] = {t.x, t.y, t.z, t.w};
#pragma unroll
        for (int ii = 0; ii < 8; ii++)
#pragma unroll
            for (int jj = 0; jj < 4; jj++) {
                accA[ii][jj] += av[ii] * qv[jj];
                accB[ii][jj] += av[ii] * tv[jj];
            }
    }

#pragma unroll
    for (int ii = 0; ii < 8; ii++) {
        int gi = i0 + ty * 4 + (ii & 3) + ((ii >= 4) ? 32 : 0);
        if (gi >= CL_) continue;
        float4 cv = *(const float4*)(cb + (size_t)gi * H_ + h0 + tx * 4);
        float4 av = make_float4(accA[ii][0], accA[ii][1], accA[ii][2], accA[ii][3]);
        float4 bv = make_float4(accB[ii][0], accB[ii][1], accB[ii][2], accB[ii][3]);
        float* o = out + (size_t)(b * CL_ + gi) * (4 * H_) + h0 + tx * 4;
        *(float4*)(o)          = cv;
        *(float4*)(o + H_)     = av;
        *(float4*)(o + 2*H_)   = make_float4(cv.x*av.x, cv.y*av.y, cv.z*av.z, cv.w*av.w);
        *(float4*)(o + 3*H_)   = make_float4(cv.x*bv.x, cv.y*bv.y, cv.z*bv.z, cv.w*bv.w);
    }
}

// ============================================================
extern "C" void kernel_launch(void* const* d_in, const int* in_sizes, int n_in,
                              void* d_out, int out_size)
{
    const float* c    = (const float*)d_in[0];
    const float* q    = (const float*)d_in[1];
    const int*   cmask= (const int*)  d_in[2];
    const int*   qmask= (const int*)  d_in[3];
    const float* cw   = (const float*)d_in[4];
    const float* qw   = (const float*)d_in[5];
    const float* cqw  = (const float*)d_in[6];
    const float* bias = (const float*)d_in[7];
    float* out = (float*)d_out;

    cudaFuncSetAttribute(k_s2tc, cudaFuncAttributeMaxDynamicSharedMemorySize, SMEM_S2TC);

    k_qpad   <<<4096, 256>>>(q, cqw, qw);
    k_simgemm<<<dim3(7, B_), 64>>>(c, cw);
    k_soft1  <<<3200, 256>>>(qmask, bias);
    k_s2red  <<<B_ * 8, 256>>>(cmask, bias);
    k_s2tc   <<<dim3(8, B_), 128, SMEM_S2TC>>>(c, cmask, bias);
    k_out    <<<dim3(7, 16, B_), 128>>>(c, out);
}

// round 15
// speedup vs baseline: 1.0304x; 1.0304x over previous
#include <cuda_runtime.h>
#include <cstdint>

// Attention_18021682774359: BiDAF-style context-query attention.
// B=64, CL=400, QL=50, H=1024. Output [B, CL, 4H] fp32.
//
// Round 15: softmax reductions fused into K1's epilogue (where G rows live
// in registers): s1 written directly (k_soft1 deleted); per-column masked
// online (M,S) partials per i-tile -> g_pM/g_pS. k_soft2w is normalize-only.
// g_qpad dropped (K4 stages q directly with a row predicate).

namespace {
constexpr int B_  = 64;
constexpr int CL_ = 400;
constexpr int QL_ = 50;
constexpr int H_  = 1024;
constexpr int QS_ = 64;   // padded QL
constexpr int NT_ = 7;    // i-tiles per batch
}

// -------- scratch (device globals; allocation-free) --------
__device__ float g_G    [B_*CL_*QS_];
__device__ float g_s1   [B_*CL_*QS_];
__device__ float g_s2   [B_*CL_*QS_];
__device__ float g_qpadw[B_*QS_*H_];    // q * cqw, zero-padded rows
__device__ float g_t    [B_*QS_*H_];
__device__ float g_cdot [B_*CL_];
__device__ float g_qdot [B_*QS_];
__device__ float g_pM   [B_*NT_*QS_];   // s2 per-i-tile partial max
__device__ float g_pS   [B_*NT_*QS_];   // s2 per-i-tile partial sum

__device__ __forceinline__ unsigned smem_u32(const void* p) {
    return (unsigned)__cvta_generic_to_shared(p);
}
__device__ __forceinline__ void cp_async16(unsigned dst, const void* src, bool pred) {
    int sz = pred ? 16 : 0;
    asm volatile("cp.async.cg.shared.global [%0], [%1], 16, %2;"
                 :: "r"(dst), "l"(src), "r"(sz) : "memory");
}
__device__ __forceinline__ void cp_commit() {
    asm volatile("cp.async.commit_group;" ::: "memory");
}

// ============================================================
// K0: qpadw = q * cqw (zero-padded) + fused qdot (block == one (b,j) row)
// ============================================================
__global__ __launch_bounds__(256) void k_qpad(
    const float* __restrict__ q, const float* __restrict__ cqw,
    const float* __restrict__ qw)
{
    __shared__ float red[8];
    int blk = blockIdx.x;            // b*64 + j
    int j = blk & 63, b = blk >> 6;
    int h4 = threadIdx.x;            // 0..255 float4 position
    float4 v = make_float4(0.f, 0.f, 0.f, 0.f);
    if (j < QL_) v = ((const float4*)q)[(b * QL_ + j) * 256 + h4];
    float4 w = ((const float4*)cqw)[h4];
    ((float4*)g_qpadw)[(blk << 8) + h4] = make_float4(v.x*w.x, v.y*w.y, v.z*w.z, v.w*w.w);

    float4 ww = ((const float4*)qw)[h4];
    float s = v.x*ww.x + v.y*ww.y + v.z*ww.z + v.w*ww.w;
#pragma unroll
    for (int o = 16; o; o >>= 1) s += __shfl_xor_sync(0xffffffffu, s, o);
    int lane = threadIdx.x & 31, wid = threadIdx.x >> 5;
    if (lane == 0) red[wid] = s;
    __syncthreads();
    if (threadIdx.x == 0) {
        float t = 0.f;
#pragma unroll
        for (int r = 0; r < 8; r++) t += red[r];
        g_qdot[blk] = t;
    }
}

// ============================================================
// K1: G[b, i-tile 64, j 64] = c @ qpadw^T, K=1024 (32 chunks of 32).
// 64 threads, micro 8x8, k-vectorized, crosswise swizzle, cp.async.
// Fused epilogue: cdot (tx==0), row softmax -> s1, column (M,S) partials.
// ============================================================
__global__ __launch_bounds__(64) void k_simgemm(
    const float* __restrict__ c, const float* __restrict__ cw,
    const int* __restrict__ qmask, const int* __restrict__ cmask,
    const float* __restrict__ bias)
{
    __shared__ float4 As4[2][512];   // 64 rows x 8 kgroups
    __shared__ float4 Bs4[2][512];
    __shared__ float4 CwS[2][8];
    int b  = blockIdx.y;
    int i0 = blockIdx.x * 64;
    int tid = threadIdx.x, tx = tid & 7, ty = tid >> 3;
    const float* cb = c        + (size_t)b * CL_ * H_;
    const float* qb = g_qpadw  + (size_t)b * QS_ * H_;

    float acc[8][8];
#pragma unroll
    for (int i = 0; i < 8; i++)
#pragma unroll
        for (int j = 0; j < 8; j++) acc[i][j] = 0.f;
    float cd[8];
#pragma unroll
    for (int i = 0; i < 8; i++) cd[i] = 0.f;

    auto stage = [&](int ch, int buf) {
        int kc = ch * 32;
#pragma unroll
        for (int u = 0; u < 8; u++) {
            int idx = tid + 64 * u;
            int m = idx >> 3, kg = idx & 7;
            bool p = (i0 + m) < CL_;
            const float* src = cb + (size_t)(p ? (i0 + m) : 0) * H_ + kc + kg * 4;
            cp_async16(smem_u32(&As4[buf][m * 8 + (kg ^ ((m >> 2) & 7))]), src, p);
        }
#pragma unroll
        for (int u = 0; u < 8; u++) {
            int idx = tid + 64 * u;
            int n = idx >> 3, kg = idx & 7;
            cp_async16(smem_u32(&Bs4[buf][n * 8 + (kg ^ ((n >> 2) & 7))]),
                       qb + (size_t)n * H_ + kc + kg * 4, true);
        }
        if (tid < 8) cp_async16(smem_u32(&CwS[buf][tid]), cw + kc + tid * 4, true);
        cp_commit();
    };

    stage(0, 0);
    for (int ch = 0; ch < 32; ch++) {
        int buf = ch & 1;
        if (ch < 31) {
            stage(ch + 1, buf ^ 1);
            asm volatile("cp.async.wait_group 1;" ::: "memory");
        } else {
            asm volatile("cp.async.wait_group 0;" ::: "memory");
        }
        __syncthreads();
#pragma unroll 1
        for (int kg = 0; kg < 8; kg++) {
            float4 a4[8], b4[8];
#pragma unroll
            for (int ii = 0; ii < 4; ii++) {
                a4[ii]     = As4[buf][(ty * 4 + ii)      * 8 + (kg ^ ty)];
                a4[ii + 4] = As4[buf][(ty * 4 + 32 + ii) * 8 + (kg ^ ty)];
                b4[ii]     = Bs4[buf][(tx * 4 + ii)      * 8 + (kg ^ tx)];
                b4[ii + 4] = Bs4[buf][(tx * 4 + 32 + ii) * 8 + (kg ^ tx)];
            }
            if (tx == 0) {
                float4 w4 = CwS[buf][kg];
#pragma unroll
                for (int ii = 0; ii < 8; ii++)
                    cd[ii] += a4[ii].x*w4.x + a4[ii].y*w4.y + a4[ii].z*w4.z + a4[ii].w*w4.w;
            }
#pragma unroll
            for (int ii = 0; ii < 8; ii++)
#pragma unroll
                for (int jj = 0; jj < 8; jj++) {
                    acc[ii][jj] += a4[ii].x * b4[jj].x + a4[ii].y * b4[jj].y
                                 + a4[ii].z * b4[jj].z + a4[ii].w * b4[jj].w;
                }
        }
        __syncthreads();
    }

    // ================= fused epilogue =================
    float* qd  = (float*)As4;          // 64 floats: qdot + bias
    int*   qm  = ((int*)As4) + 64;     // 64 ints:   qmask (pad 0)
    float* colM = (float*)Bs4;         // 8 ty x 64 cols
    float* colS = ((float*)Bs4) + 512;

    if (tid < 64) {
        qd[tid] = g_qdot[b * QS_ + tid] + bias[0];
        qm[tid] = (tid < QL_) ? qmask[b * QL_ + tid] : 0;
    }
    __syncthreads();

    float cdr[8];
#pragma unroll
    for (int ii = 0; ii < 8; ii++)
        cdr[ii] = __shfl_sync(0xffffffffu, cd[ii], (threadIdx.x & 31) & ~7);

    int cols[8];
#pragma unroll
    for (int jj = 0; jj < 8; jj++) cols[jj] = tx * 4 + (jj & 3) + ((jj >= 4) ? 32 : 0);

    // ---- store G; row softmax -> s1 ----
#pragma unroll
    for (int ii = 0; ii < 8; ii++) {
        int gi = i0 + ty * 4 + (ii & 3) + ((ii >= 4) ? 32 : 0);
        if (gi >= CL_) continue;
        float* g = g_G + ((size_t)(b * CL_ + gi) << 6);
        *(float4*)(g + tx * 4)      = make_float4(acc[ii][0], acc[ii][1], acc[ii][2], acc[ii][3]);
        *(float4*)(g + tx * 4 + 32) = make_float4(acc[ii][4], acc[ii][5], acc[ii][6], acc[ii][7]);

        float v[8];
        float m = -1e38f;
#pragma unroll
        for (int jj = 0; jj < 8; jj++) {
            int cj = cols[jj];
            float val = acc[ii][jj] + cdr[ii] + qd[cj];
            v[jj] = (cj < QL_) ? (qm[cj] ? val : -1e30f) : -1e38f;
            m = fmaxf(m, v[jj]);
        }
        m = fmaxf(m, __shfl_xor_sync(0xffffffffu, m, 1));
        m = fmaxf(m, __shfl_xor_sync(0xffffffffu, m, 2));
        m = fmaxf(m, __shfl_xor_sync(0xffffffffu, m, 4));
        float e[8], s = 0.f;
#pragma unroll
        for (int jj = 0; jj < 8; jj++) {
            e[jj] = (cols[jj] < QL_) ? expf(v[jj] - m) : 0.f;
            s += e[jj];
        }
        s += __shfl_xor_sync(0xffffffffu, s, 1);
        s += __shfl_xor_sync(0xffffffffu, s, 2);
        s += __shfl_xor_sync(0xffffffffu, s, 4);
        float inv = 1.f / s;
        float* s1p = g_s1 + ((size_t)(b * CL_ + gi) << 6);
        *(float4*)(s1p + tx * 4)      = make_float4(e[0]*inv, e[1]*inv, e[2]*inv, e[3]*inv);
        *(float4*)(s1p + tx * 4 + 32) = make_float4(e[4]*inv, e[5]*inv, e[6]*inv, e[7]*inv);
    }
    if (tx == 0) {
#pragma unroll
        for (int ii = 0; ii < 8; ii++) {
            int gi = i0 + ty * 4 + (ii & 3) + ((ii >= 4) ? 32 : 0);
            if (gi < CL_) g_cdot[b * CL_ + gi] = cd[ii];
        }
    }

    // ---- column (M,S) partials over this i-tile's 64 rows ----
    int cmr[8];
#pragma unroll
    for (int ii = 0; ii < 8; ii++) {
        int gi = i0 + ty * 4 + (ii & 3) + ((ii >= 4) ? 32 : 0);
        cmr[ii] = (gi < CL_) ? cmask[b * CL_ + gi] : -1;   // -1 = pad row
    }
#pragma unroll
    for (int jj = 0; jj < 8; jj++) {
        int cj = cols[jj];
        float m = -1e38f, s = 0.f;
#pragma unroll
        for (int ii = 0; ii < 8; ii++) {
            if (cmr[ii] < 0) continue;
            float val = acc[ii][jj] + cdr[ii] + qd[cj];
            float vv = cmr[ii] ? val : -1e30f;
            if (vv > m) { s = s * expf(m - vv) + 1.f; m = vv; }
            else        { s += expf(vv - m); }
        }
        colM[ty * 64 + cj] = m;
        colS[ty * 64 + cj] = s;
    }
    __syncthreads();
    if (tid < 64) {
        float M = colM[tid], S = colS[tid];
#pragma unroll
        for (int u = 1; u < 8; u++) {
            float m2 = colM[u * 64 + tid], s2 = colS[u * 64 + tid];
            if (m2 > M) { S = S * expf(M - m2) + s2; M = m2; }
            else        { S += s2 * expf(m2 - M); }
        }
        size_t po = ((size_t)b * NT_ + blockIdx.x) * QS_ + tid;
        g_pM[po] = M;
        g_pS[po] = S;
    }
}

// ============================================================
// K2: soft2 normalize-only. Block (b, z): rows [z*50,(z+1)*50).
// 256 threads = 4 r x 64 j. Combine 7 i-tile partials, then coalesced
// read-G / write-s2 pass (pads j>=50 to zero).
// ============================================================
__global__ __launch_bounds__(256) void k_soft2w(
    const int* __restrict__ cmask, const float* __restrict__ bias)
{
    __shared__ float Mf[64], Sf[64];
    int blk = blockIdx.x;            // b*8 + z
    int z = blk & 7, b = blk >> 3;
    int j = threadIdx.x & 63;
    int r = threadIdx.x >> 6;        // 0..3

    if (threadIdx.x < 64) {
        float M = g_pM[(size_t)b * NT_ * QS_ + threadIdx.x];
        float S = g_pS[(size_t)b * NT_ * QS_ + threadIdx.x];
#pragma unroll
        for (int u = 1; u < NT_; u++) {
            float m2 = g_pM[((size_t)b * NT_ + u) * QS_ + threadIdx.x];
            float s2 = g_pS[((size_t)b * NT_ + u) * QS_ + threadIdx.x];
            if (m2 > M) { S = S * expf(M - m2) + s2; M = m2; }
            else        { S += s2 * expf(m2 - M); }
        }
        Mf[threadIdx.x] = M; Sf[threadIdx.x] = 1.f / S;
    }
    __syncthreads();
    float M = Mf[j], invS = Sf[j];
    float qd = g_qdot[b * QS_ + j] + bias[0];

    int i1 = (z + 1) * 50;
    if (j < QL_) {
        for (int i = z * 50 + r; i < i1; i += 4) {
            size_t off = ((size_t)(b * CL_ + i) << 6) + j;
            float v = g_G[off] + g_cdot[b * CL_ + i] + qd;
            v = cmask[b * CL_ + i] ? v : -1e30f;
            g_s2[off] = expf(v - M) * invS;
        }
    } else {
        for (int i = z * 50 + r; i < i1; i += 4)
            g_s2[((size_t)(b * CL_ + i) << 6) + j] = 0.f;
    }
}

// ============================================================
// K3: t[b, j 64, h-tile 128] = s2^T @ c, K=CL (13 chunks of 32).
// 128 threads, micro 8x8, outer-product, cp.async.
// ============================================================
__global__ __launch_bounds__(128) void k_s2tc(const float* __restrict__ c)
{
    __shared__ float4 As4[2][512];    // [k 32][m-groups 16]
    __shared__ float4 Bs4[2][1024];   // [k 32][n-groups 32]
    int b  = blockIdx.y;
    int h0 = blockIdx.x * 128;
    int tid = threadIdx.x, tx = tid & 15, ty = tid >> 4;

    float acc[8][8];
#pragma unroll
    for (int i = 0; i < 8; i++)
#pragma unroll
        for (int j = 0; j < 8; j++) acc[i][j] = 0.f;

    auto stage = [&](int ch, int buf) {
        int kc = ch * 32;
#pragma unroll
        for (int u = 0; u < 4; u++) {
            int idx = tid + 128 * u;
            int il = idx >> 4, jg = idx & 15;
            bool p = (kc + il) < CL_;
            const float* src = g_s2 + ((size_t)(b * CL_ + (p ? kc + il : 0)) << 6) + jg * 4;
            cp_async16(smem_u32(&As4[buf][il * 16 + (jg ^ ((il >> 2) & 7))]), src, p);
        }
#pragma unroll
        for (int u = 0; u < 8; u++) {
            int idx = tid + 128 * u;
            int il = idx >> 5, hg = idx & 31;
            bool p = (kc + il) < CL_;
            const float* src = c + (size_t)(b * CL_ + (p ? kc + il : 0)) * H_ + h0 + hg * 4;
            cp_async16(smem_u32(&Bs4[buf][il * 32 + (hg ^ ((il >> 2) & 7))]), src, p);
        }
        cp_commit();
    };

    stage(0, 0);
    for (int ch = 0; ch < 13; ch++) {
        int buf = ch & 1;
        if (ch < 12) {
            stage(ch + 1, buf ^ 1);
            asm volatile("cp.async.wait_group 1;" ::: "memory");
        } else {
            asm volatile("cp.async.wait_group 0;" ::: "memory");
        }
        __syncthreads();
#pragma unroll 4
        for (int kk = 0; kk < 32; kk++) {
            int s = (kk >> 2) & 7;
            float4 a0 = As4[buf][kk * 16 + (ty ^ s)];
            float4 a1 = As4[buf][kk * 16 + ((ty + 8) ^ s)];
            float4 b0 = Bs4[buf][kk * 32 + (tx ^ s)];
            float4 b1 = Bs4[buf][kk * 32 + ((tx + 16) ^ s)];
            float av[8] = {a0.x,a0.y,a0.z,a0.w, a1.x,a1.y,a1.z,a1.w};
            float bv[8] = {b0.x,b0.y,b0.z,b0.w, b1.x,b1.y,b1.z,b1.w};
#pragma unroll
            for (int ii = 0; ii < 8; ii++)
#pragma unroll
                for (int jj = 0; jj < 8; jj++) acc[ii][jj] += av[ii] * bv[jj];
        }
        __syncthreads();
    }

#pragma unroll
    for (int ii = 0; ii < 8; ii++) {
        int j = ty * 4 + (ii & 3) + ((ii >= 4) ? 32 : 0);
        float* gt = g_t + (size_t)(b * QS_ + j) * H_ + h0;
        *(float4*)(gt + tx * 4)      = make_float4(acc[ii][0], acc[ii][1], acc[ii][2], acc[ii][3]);
        *(float4*)(gt + tx * 4 + 64) = make_float4(acc[ii][4], acc[ii][5], acc[ii][6], acc[ii][7]);
    }
}

// ============================================================
// K4: a = s1 @ qpad, bb = s1 @ t (K=64 resident), fused epilogue
//     out = [c, a, c*a, c*bb]. 128 threads, dual micro 8x4.
//     BQ staged straight from q with a row predicate (no g_qpad array).
// ============================================================
__global__ __launch_bounds__(128) void k_out(
    const float* __restrict__ c, const float* __restrict__ q,
    float* __restrict__ out)
{
    __shared__ float  As[64][64];    // [j][i] swizzled (s1^T)
    __shared__ float4 BQ4[1024];     // [j][h-groups 16]
    __shared__ float4 BT4[1024];
    int b  = blockIdx.z;
    int h0 = blockIdx.y * 64;
    int i0 = blockIdx.x * 64;
    int tid = threadIdx.x, tx = tid & 15, ty = tid >> 4;
    const float* cb = c + (size_t)b * CL_ * H_;

#pragma unroll
    for (int u = 0; u < 8; u++) {
        int idx = tid + 128 * u;
        int il = idx >> 4, jg = idx & 15;
        int gi = i0 + il;
        float4 v = make_float4(0.f, 0.f, 0.f, 0.f);
        if (gi < CL_) v = *(const float4*)(g_s1 + ((size_t)(b * CL_ + gi) << 6) + jg * 4);
        int colb = (((il >> 2) ^ (jg & 7)) << 2) | (il & 3);
        As[jg*4+0][colb] = v.x; As[jg*4+1][colb] = v.y;
        As[jg*4+2][colb] = v.z; As[jg*4+3][colb] = v.w;
    }
#pragma unroll
    for (int u = 0; u < 8; u++) {
        int idx = tid + 128 * u;
        int jl = idx >> 4, hg = idx & 15;
        int d = jl * 16 + (hg ^ ((jl >> 2) & 7));
        float4 qv = make_float4(0.f, 0.f, 0.f, 0.f);
        if (jl < QL_) qv = *(const float4*)(q + (size_t)(b * QL_ + jl) * H_ + h0 + hg * 4);
        BQ4[d] = qv;
        BT4[d] = *(const float4*)(g_t + (size_t)(b * QS_ + jl) * H_ + h0 + hg * 4);
    }
    __syncthreads();

    float accA[8][4], accB[8][4];
#pragma unroll
    for (int i = 0; i < 8; i++)
#pragma unroll
        for (int j = 0; j < 4; j++) { accA[i][j] = 0.f; accB[i][j] = 0.f; }

#pragma unroll 4
    for (int kk = 0; kk < 64; kk++) {
        int s = (kk >> 2) & 7;
        float4 a0 = *(const float4*)&As[kk][(ty ^ s) << 2];
        float4 a1 = *(const float4*)&As[kk][((ty + 8) ^ s) << 2];
        float4 qv = BQ4[kk * 16 + (tx ^ s)];
        float4 tv = BT4[kk * 16 + (tx ^ s)];
        float av[8] = {a0.x,a0.y,a0.z,a0.w, a1.x,a1.y,a1.z,a1.w};
        float q_[4] = {qv.x, qv.y, qv.z, qv.w};
        float t_[4] = {tv.x, tv.y, tv.z, tv.w};
#pragma unroll
        for (int ii = 0; ii < 8; ii++)
#pragma unroll
            for (int jj = 0; jj < 4; jj++) {
                accA[ii][jj] += av[ii] * q_[jj];
                accB[ii][jj] += av[ii] * t_[jj];
            }
    }

#pragma unroll
    for (int ii = 0; ii < 8; ii++) {
        int gi = i0 + ty * 4 + (ii & 3) + ((ii >= 4) ? 32 : 0);
        if (gi >= CL_) continue;
        float4 cv = *(const float4*)(cb + (size_t)gi * H_ + h0 + tx * 4);
        float4 av = make_float4(accA[ii][0], accA[ii][1], accA[ii][2], accA[ii][3]);
        float4 bv = make_float4(accB[ii][0], accB[ii][1], accB[ii][2], accB[ii][3]);
        float* o = out + (size_t)(b * CL_ + gi) * (4 * H_) + h0 + tx * 4;
        *(float4*)(o)          = cv;
        *(float4*)(o + H_)     = av;
        *(float4*)(o + 2*H_)   = make_float4(cv.x*av.x, cv.y*av.y, cv.z*av.z, cv.w*av.w);
        *(float4*)(o + 3*H_)   = make_float4(cv.x*bv.x, cv.y*bv.y, cv.z*bv.z, cv.w*bv.w);
    }
}

// ============================================================
extern "C" void kernel_launch(void* const* d_in, const int* in_sizes, int n_in,
                              void* d_out, int out_size)
{
    const float* c    = (const float*)d_in[0];
    const float* q    = (const float*)d_in[1];
    const int*   cmask= (const int*)  d_in[2];
    const int*   qmask= (const int*)  d_in[3];
    const float* cw   = (const float*)d_in[4];
    const float* qw   = (const float*)d_in[5];
    const float* cqw  = (const float*)d_in[6];
    const float* bias = (const float*)d_in[7];
    float* out = (float*)d_out;

    k_qpad   <<<4096, 256>>>(q, cqw, qw);
    k_simgemm<<<dim3(NT_, B_), 64>>>(c, cw, qmask, cmask, bias);
    k_soft2w <<<B_ * 8, 256>>>(cmask, bias);
    k_s2tc   <<<dim3(8, B_), 128>>>(c);
    k_out    <<<dim3(7, 16, B_), 128>>>(c, q, out);
}